// round 1
// baseline (speedup 1.0000x reference)
#include <cuda_runtime.h>

#define SB   32      // S*B
#define NTOK 2048    // N
#define KK   16      // K
#define DD   32      // D
#define HH   128     // H

// Scratch for hk[k,h] + b1[h] per (s,b). 32*16*128 floats = 256 KB.
__device__ float g_hkb[SB * KK * HH];

__device__ __forceinline__ float tanhfast(float v) {
    float y;
    asm("tanh.approx.f32 %0, %1;" : "=f"(y) : "f"(v));
    return y;
}

// ---------------------------------------------------------------------------
// Prep: hkb[sb,k,h] = sum_d mu[sb,k,d]*Wm[d,h] + tau[sb,k,d]*Wt[d,h] + b1[h]
// Tiny: 32 blocks x 128 threads, ~1k FMA per thread.
// ---------------------------------------------------------------------------
__global__ void prep_kernel(const float* __restrict__ mu,
                            const float* __restrict__ tau,
                            const float* __restrict__ W1,
                            const float* __restrict__ b1) {
    int sb = blockIdx.x;
    int h  = threadIdx.x;
    const float* mub  = mu  + sb * KK * DD;
    const float* taub = tau + sb * KK * DD;
    float bb = b1[h];
    #pragma unroll 1
    for (int k = 0; k < KK; k++) {
        float s = bb;
        #pragma unroll
        for (int d = 0; d < DD; d++) {
            s = fmaf(mub [k * DD + d], W1[(DD     + d) * HH + h], s);
            s = fmaf(taub[k * DD + d], W1[(2 * DD + d) * HH + h], s);
        }
        g_hkb[sb * KK * HH + k * HH + h] = s;
    }
}

// ---------------------------------------------------------------------------
// Main: one thread per token n. For each n:
//   hx[h] = x[n,:] . Wx[:,h]                (computed in h-chunks of 16)
//   gamma[k] = sum_h tanh(hx[h] + hkb[k,h]) * W2[h]
//   out[n,:] = softmax_k(gamma)             (b2 drops out of softmax exactly)
// ---------------------------------------------------------------------------
__global__ __launch_bounds__(128, 4)
void main_kernel(const float* __restrict__ x,
                 const float* __restrict__ W1,
                 const float* __restrict__ W2,
                 float* __restrict__ out) {
    __shared__ float Wx_s[DD * HH];   // 16 KB
    __shared__ float hkb_s[KK * HH];  //  8 KB
    __shared__ float w2_s[HH];        // 0.5 KB

    const int tid = threadIdx.x;
    const int sb  = blockIdx.y;
    const int n   = blockIdx.x * 128 + tid;

    // Cooperative smem fill (all loads coalesced)
    for (int i = tid; i < DD * HH; i += 128) Wx_s[i]  = W1[i];            // rows 0..31 of W1
    for (int i = tid; i < KK * HH; i += 128) hkb_s[i] = g_hkb[sb * KK * HH + i];
    if (tid < HH) w2_s[tid] = W2[tid];
    __syncthreads();

    // x row (32 floats, 128B aligned) into registers
    float xr[DD];
    const float4* xp = reinterpret_cast<const float4*>(x + ((size_t)sb * NTOK + n) * DD);
    #pragma unroll
    for (int i = 0; i < 8; i++) {
        float4 v = xp[i];
        xr[4 * i + 0] = v.x; xr[4 * i + 1] = v.y;
        xr[4 * i + 2] = v.z; xr[4 * i + 3] = v.w;
    }

    float acc[KK];
    #pragma unroll
    for (int k = 0; k < KK; k++) acc[k] = 0.f;

    // h-chunks of 16: hx chunk in regs, then sweep all 16 k.
    #pragma unroll 1
    for (int hc = 0; hc < HH; hc += 16) {
        float hx[16];
        #pragma unroll
        for (int j = 0; j < 16; j++) hx[j] = 0.f;

        #pragma unroll
        for (int d = 0; d < DD; d++) {
            float xd = xr[d];
            const float4* wrow = reinterpret_cast<const float4*>(&Wx_s[d * HH + hc]);
            #pragma unroll
            for (int q = 0; q < 4; q++) {
                float4 w = wrow[q];   // warp-uniform broadcast LDS.128
                hx[4 * q + 0] = fmaf(xd, w.x, hx[4 * q + 0]);
                hx[4 * q + 1] = fmaf(xd, w.y, hx[4 * q + 1]);
                hx[4 * q + 2] = fmaf(xd, w.z, hx[4 * q + 2]);
                hx[4 * q + 3] = fmaf(xd, w.w, hx[4 * q + 3]);
            }
        }

        float w2c[16];
        const float4* w2p = reinterpret_cast<const float4*>(&w2_s[hc]);
        #pragma unroll
        for (int q = 0; q < 4; q++) {
            float4 w = w2p[q];
            w2c[4 * q + 0] = w.x; w2c[4 * q + 1] = w.y;
            w2c[4 * q + 2] = w.z; w2c[4 * q + 3] = w.w;
        }

        #pragma unroll
        for (int k = 0; k < KK; k++) {
            const float4* hkp = reinterpret_cast<const float4*>(&hkb_s[k * HH + hc]);
            float a = acc[k];
            #pragma unroll
            for (int q = 0; q < 4; q++) {
                float4 hv = hkp[q];   // warp-uniform broadcast LDS.128
                a = fmaf(tanhfast(hx[4 * q + 0] + hv.x), w2c[4 * q + 0], a);
                a = fmaf(tanhfast(hx[4 * q + 1] + hv.y), w2c[4 * q + 1], a);
                a = fmaf(tanhfast(hx[4 * q + 2] + hv.z), w2c[4 * q + 2], a);
                a = fmaf(tanhfast(hx[4 * q + 3] + hv.w), w2c[4 * q + 3], a);
            }
            acc[k] = a;
        }
    }

    // Softmax over K=16, in registers. b2 is a uniform shift -> cancels exactly.
    float m = acc[0];
    #pragma unroll
    for (int k = 1; k < KK; k++) m = fmaxf(m, acc[k]);
    float e[KK], s = 0.f;
    #pragma unroll
    for (int k = 0; k < KK; k++) { e[k] = __expf(acc[k] - m); s += e[k]; }
    float inv = __fdividef(1.f, s);

    float4* op = reinterpret_cast<float4*>(out + ((size_t)sb * NTOK + n) * KK);
    #pragma unroll
    for (int q = 0; q < 4; q++) {
        float4 v;
        v.x = e[4 * q + 0] * inv; v.y = e[4 * q + 1] * inv;
        v.z = e[4 * q + 2] * inv; v.w = e[4 * q + 3] * inv;
        op[q] = v;
    }
}

extern "C" void kernel_launch(void* const* d_in, const int* in_sizes, int n_in,
                              void* d_out, int out_size) {
    const float* x   = (const float*)d_in[0];
    const float* mu  = (const float*)d_in[1];
    const float* tau = (const float*)d_in[2];
    const float* W1  = (const float*)d_in[3];
    const float* b1  = (const float*)d_in[4];
    const float* W2  = (const float*)d_in[5];
    // d_in[6] = b2: provably cancels in softmax, unused.
    float* out = (float*)d_out;

    prep_kernel<<<SB, HH>>>(mu, tau, W1, b1);
    main_kernel<<<dim3(NTOK / 128, SB), 128>>>(x, W1, W2, out);
}

// round 2
// speedup vs baseline: 1.2124x; 1.2124x over previous
#include <cuda_runtime.h>

#define SB   32      // S*B
#define NTOK 2048    // N
#define KK   16      // K
#define DD   32      // D
#define HH   128     // H

typedef unsigned long long u64;

// Scratch for hk[k,h] + b1[h] per (s,b). 32*16*128 floats = 256 KB.
__device__ float g_hkb[SB * KK * HH];

__device__ __forceinline__ float tanhfast(float v) {
    float y;
    asm("tanh.approx.f32 %0, %1;" : "=f"(y) : "f"(v));
    return y;
}
__device__ __forceinline__ u64 pk2(float lo, float hi) {
    u64 r; asm("mov.b64 %0, {%1, %2};" : "=l"(r) : "f"(lo), "f"(hi)); return r;
}
__device__ __forceinline__ void upk2(float& lo, float& hi, u64 v) {
    asm("mov.b64 {%0, %1}, %2;" : "=f"(lo), "=f"(hi) : "l"(v));
}
__device__ __forceinline__ u64 add2(u64 a, u64 b) {
    u64 r; asm("add.rn.f32x2 %0, %1, %2;" : "=l"(r) : "l"(a), "l"(b)); return r;
}
__device__ __forceinline__ u64 fma2(u64 a, u64 b, u64 c) {
    u64 r; asm("fma.rn.f32x2 %0, %1, %2, %3;" : "=l"(r) : "l"(a), "l"(b), "l"(c)); return r;
}

// ---------------------------------------------------------------------------
// Prep: hkb[sb,k,h] = sum_d mu[sb,k,d]*Wm[d,h] + tau[sb,k,d]*Wt[d,h] + b1[h]
// One block per (k, sb): 512 blocks x 128 threads, 64 FMA per thread.
// ---------------------------------------------------------------------------
__global__ void prep_kernel(const float* __restrict__ mu,
                            const float* __restrict__ tau,
                            const float* __restrict__ W1,
                            const float* __restrict__ b1) {
    int k  = blockIdx.x;
    int sb = blockIdx.y;
    int h  = threadIdx.x;
    const float* mur  = mu  + (sb * KK + k) * DD;
    const float* taur = tau + (sb * KK + k) * DD;
    float s = b1[h];
    #pragma unroll
    for (int d = 0; d < DD; d++) {
        s = fmaf(mur [d], W1[(DD     + d) * HH + h], s);
        s = fmaf(taur[d], W1[(2 * DD + d) * HH + h], s);
    }
    g_hkb[(sb * KK + k) * HH + h] = s;
}

// ---------------------------------------------------------------------------
// Main: one thread per token n.
//   hx[h] = x[n,:] . Wx[:,h]                (h-chunks of 16, packed f32x2)
//   gamma[k] = sum_h tanh(hx[h] + hkb[k,h]) * W2[h]
//   out[n,:] = softmax_k(gamma)             (b2 cancels exactly)
// ---------------------------------------------------------------------------
__global__ __launch_bounds__(128, 5)
void main_kernel(const float* __restrict__ x,
                 const float* __restrict__ W1,
                 const float* __restrict__ W2,
                 float* __restrict__ out) {
    __shared__ float Wx_s[DD * HH];   // 16 KB
    __shared__ float hkb_s[KK * HH];  //  8 KB
    __shared__ float w2_s[HH];        // 0.5 KB

    const int tid = threadIdx.x;
    const int sb  = blockIdx.y;
    const int n   = blockIdx.x * 128 + tid;

    for (int i = tid; i < DD * HH; i += 128) Wx_s[i]  = W1[i];   // rows 0..31 of W1
    for (int i = tid; i < KK * HH; i += 128) hkb_s[i] = g_hkb[sb * KK * HH + i];
    if (tid < HH) w2_s[tid] = W2[tid];
    __syncthreads();

    // x row (32 floats) into registers
    float xr[DD];
    const float4* xp = reinterpret_cast<const float4*>(x + ((size_t)sb * NTOK + n) * DD);
    #pragma unroll
    for (int i = 0; i < 8; i++) {
        float4 v = xp[i];
        xr[4 * i + 0] = v.x; xr[4 * i + 1] = v.y;
        xr[4 * i + 2] = v.z; xr[4 * i + 3] = v.w;
    }

    float acc[KK];
    #pragma unroll
    for (int k = 0; k < KK; k++) acc[k] = 0.f;

    #pragma unroll 1
    for (int hc = 0; hc < HH; hc += 16) {
        // ---- hx chunk (8 f32x2 pairs) via packed FFMA2 ----
        u64 hx2[8];
        #pragma unroll
        for (int j = 0; j < 8; j++) hx2[j] = 0ull;

        #pragma unroll
        for (int d = 0; d < DD; d++) {
            u64 xd2 = pk2(xr[d], xr[d]);
            const ulonglong2* wrow = reinterpret_cast<const ulonglong2*>(&Wx_s[d * HH + hc]);
            #pragma unroll
            for (int q = 0; q < 4; q++) {
                ulonglong2 w = wrow[q];       // broadcast LDS.128 -> 2 f32x2 pairs
                hx2[2 * q + 0] = fma2(xd2, w.x, hx2[2 * q + 0]);
                hx2[2 * q + 1] = fma2(xd2, w.y, hx2[2 * q + 1]);
            }
        }

        float w2c[16];
        const float4* w2p = reinterpret_cast<const float4*>(&w2_s[hc]);
        #pragma unroll
        for (int q = 0; q < 4; q++) {
            float4 w = w2p[q];
            w2c[4 * q + 0] = w.x; w2c[4 * q + 1] = w.y;
            w2c[4 * q + 2] = w.z; w2c[4 * q + 3] = w.w;
        }

        // ---- k sweep: packed add, scalar tanh + fma ----
        #pragma unroll
        for (int k = 0; k < KK; k++) {
            const ulonglong2* hkp = reinterpret_cast<const ulonglong2*>(&hkb_s[k * HH + hc]);
            float a = acc[k];
            #pragma unroll
            for (int q = 0; q < 4; q++) {
                ulonglong2 hv = hkp[q];       // broadcast LDS.128
                u64 t0 = add2(hx2[2 * q + 0], hv.x);
                u64 t1 = add2(hx2[2 * q + 1], hv.y);
                float l0, h0, l1, h1;
                upk2(l0, h0, t0);
                upk2(l1, h1, t1);
                a = fmaf(tanhfast(l0), w2c[4 * q + 0], a);
                a = fmaf(tanhfast(h0), w2c[4 * q + 1], a);
                a = fmaf(tanhfast(l1), w2c[4 * q + 2], a);
                a = fmaf(tanhfast(h1), w2c[4 * q + 3], a);
            }
            acc[k] = a;
        }
    }

    // Softmax over K=16 in registers (b2 cancels).
    float m = acc[0];
    #pragma unroll
    for (int k = 1; k < KK; k++) m = fmaxf(m, acc[k]);
    float s = 0.f;
    #pragma unroll
    for (int k = 0; k < KK; k++) { acc[k] = __expf(acc[k] - m); s += acc[k]; }
    float inv = __fdividef(1.f, s);

    float4* op = reinterpret_cast<float4*>(out + ((size_t)sb * NTOK + n) * KK);
    #pragma unroll
    for (int q = 0; q < 4; q++) {
        float4 v;
        v.x = acc[4 * q + 0] * inv; v.y = acc[4 * q + 1] * inv;
        v.z = acc[4 * q + 2] * inv; v.w = acc[4 * q + 3] * inv;
        op[q] = v;
    }
}

extern "C" void kernel_launch(void* const* d_in, const int* in_sizes, int n_in,
                              void* d_out, int out_size) {
    const float* x   = (const float*)d_in[0];
    const float* mu  = (const float*)d_in[1];
    const float* tau = (const float*)d_in[2];
    const float* W1  = (const float*)d_in[3];
    const float* b1  = (const float*)d_in[4];
    const float* W2  = (const float*)d_in[5];
    // d_in[6] = b2: cancels in softmax, unused.
    float* out = (float*)d_out;

    prep_kernel<<<dim3(KK, SB), HH>>>(mu, tau, W1, b1);
    main_kernel<<<dim3(NTOK / 128, SB), 128>>>(x, W1, W2, out);
}